// round 1
// baseline (speedup 1.0000x reference)
#include <cuda_runtime.h>

#define SDIM 26
#define SS   676          // 26*26
#define CNUM 80
#define NCH  255          // 3*(5+80)
#define NB   32
#define BATCH 256
#define DIV  16.0f        // 416/26
#define IMG  416.0f

__device__ float g_partial[BATCH];

__device__ __constant__ float c_anchor[9][2] = {
    {10.f,13.f},{16.f,30.f},{33.f,23.f},{30.f,61.f},{62.f,45.f},
    {59.f,119.f},{116.f,90.f},{156.f,198.f},{373.f,326.f}};

__device__ __forceinline__ float warp_sum(float v) {
#pragma unroll
    for (int o = 16; o > 0; o >>= 1) v += __shfl_down_sync(0xffffffffu, v, o);
    return v;
}

__global__ __launch_bounds__(256) void yolo_image_kernel(
    const float* __restrict__ x,      // (B, 255, 26, 26)
    const float* __restrict__ box,    // (B, 32, 5)
    const int*   __restrict__ bidx)   // (B, 32)
{
    const int b   = blockIdx.x;
    const int tid = threadIdx.x;
    const float* xb = x + (size_t)b * NCH * SS;

    __shared__ int   sh_base[NB];
    __shared__ int   sh_pos[NB];
    __shared__ int   sh_cls[NB];
    __shared__ float sh_wn[8];     // per-warp noobj partial
    __shared__ float sh_wl[8];     // per-warp label partial
    __shared__ float sh_scalar[3]; // boxloss, corr, ucnt

    float boxloss = 0.0f;

    // ---- per-box scalar work: warp 0 (32 lanes == 32 boxes) ----
    if (tid < NB) {
        const float* bp = box + ((size_t)b * NB + tid) * 5;
        float cls = bp[0];
        float cx  = bp[1];
        float cy  = bp[2];
        float w   = bp[3];
        float h   = bp[4];
        int   ni  = bidx[(size_t)b * NB + tid];      // 3..5
        int   base = (ni - 3) * (5 + CNUM);          // 0 / 85 / 170
        int   ix  = (int)(cx / DIV);
        int   iy  = (int)(cy / DIV);
        float ax  = (cx - (float)ix * DIV) / DIV;
        float ay  = (cy - (float)iy * DIV) / DIV;
        int   pos = ix * SDIM + iy;

        sh_base[tid] = base;
        sh_pos[tid]  = pos;
        sh_cls[tid]  = (int)cls;

        const float* xc = xb + pos;
        float obj = xc[(size_t)(base + 0) * SS];
        float rax = xc[(size_t)(base + 1) * SS];
        float ray = xc[(size_t)(base + 2) * SS];
        float s3  = xc[(size_t)(base + 3) * SS];
        float s4  = xc[(size_t)(base + 4) * SS];

        float sig3 = 1.0f / (1.0f + expf(-s3));
        float sig4 = 1.0f / (1.0f + expf(-s4));
        float rw = c_anchor[ni][0] * expf(4.0f * sig3 - 2.0f);
        float rh = c_anchor[ni][1] * expf(4.0f * sig4 - 2.0f);

        // IoU
        float b1x1 = rax * DIV - rw * 0.5f, b1y1 = ray * DIV - rh * 0.5f;
        float b1x2 = rax * DIV + rw * 0.5f, b1y2 = ray * DIV + rh * 0.5f;
        float b2x1 = ax * DIV - w * 0.5f,   b2y1 = ay * DIV - h * 0.5f;
        float b2x2 = ax * DIV + w * 0.5f,   b2y2 = ay * DIV + h * 0.5f;
        float A  = (b1x2 - b1x1 + 1.0f) * (b1y2 - b1y1 + 1.0f);
        float Bt = (b2x2 - b2x1 + 1.0f) * (b2y2 - b2y1 + 1.0f);
        float CM = (fminf(b1x2, b2x2) - fmaxf(b1x1, b2x1) + 1.0f) *
                   (fminf(b1y2, b2y2) - fmaxf(b1y1, b2y1) + 1.0f);
        float r  = CM / (A + Bt - CM);
        float iou = (r < 0.0f) ? 0.0f : r;

        float d0 = obj - iou;
        float d1 = rax - ax;
        float d2 = ray - ay;
        float d3 = (rw - w) / IMG;
        float d4 = (rh - h) / IMG;
        boxloss = d0 * d0 + d1 * d1 + d2 * d2 + d3 * d3 + d4 * d4;
    }
    __syncthreads();

    // ---- unique-triple noobj mask correction: warp 0 ----
    if (tid < 32) {
        float corr = 0.0f;
        float ucnt = 0.0f;
        int key = sh_base[tid] * SS + sh_pos[tid];
        bool uniq = true;
        for (int t2 = 0; t2 < tid; ++t2) {
            if (sh_base[t2] * SS + sh_pos[t2] == key) { uniq = false; break; }
        }
        if (uniq) {
            float v = xb[key];
            corr = v * v;
            ucnt = 1.0f;
        }
        boxloss = warp_sum(boxloss);
        corr    = warp_sum(corr);
        ucnt    = warp_sum(ucnt);
        if (tid == 0) {
            sh_scalar[0] = boxloss;
            sh_scalar[1] = corr;
            sh_scalar[2] = ucnt;
        }
    }

    // ---- label MSE over 32*80 elements: all 256 threads ----
    float lsum = 0.0f;
#pragma unroll
    for (int e = tid; e < NB * CNUM; e += 256) {
        int t = e / CNUM;
        int j = e - t * CNUM;
        float lab = xb[(size_t)(sh_base[t] + 5 + j) * SS + sh_pos[t]];
        float hot = (j == sh_cls[t]) ? 1.0f : 0.0f;
        float d = lab - hot;
        lsum += d * d;
    }

    // ---- noobj sum of squares over channels {0,85,170}: all 256 threads ----
    float nsum = 0.0f;
#pragma unroll
    for (int p = tid; p < 3 * SS; p += 256) {
        int c   = p / SS;
        int off = p - c * SS;
        float v = xb[(size_t)(c * 85) * SS + off];
        nsum += v * v;
    }

    // ---- block reduce lsum, nsum ----
    lsum = warp_sum(lsum);
    nsum = warp_sum(nsum);
    int wid = tid >> 5;
    if ((tid & 31) == 0) { sh_wl[wid] = lsum; sh_wn[wid] = nsum; }
    __syncthreads();

    if (tid == 0) {
        float lt = 0.0f, nt = 0.0f;
#pragma unroll
        for (int i = 0; i < 8; ++i) { lt += sh_wl[i]; nt += sh_wn[i]; }
        float cnt   = 3.0f * (float)SS - sh_scalar[2];
        float noobj = (nt - sh_scalar[1]) / cnt;
        float loss  = (5.0f / (float)NB) * sh_scalar[0]
                    + lt / (float)(NB * CNUM)
                    + 0.5f * noobj;
        g_partial[b] = loss;
    }
}

__global__ __launch_bounds__(256) void yolo_reduce_kernel(float* __restrict__ out)
{
    int tid = threadIdx.x;
    float v = g_partial[tid];
    v = warp_sum(v);
    __shared__ float sw[8];
    if ((tid & 31) == 0) sw[tid >> 5] = v;
    __syncthreads();
    if (tid == 0) {
        float t = 0.0f;
#pragma unroll
        for (int i = 0; i < 8; ++i) t += sw[i];
        out[0] = t;
    }
}

extern "C" void kernel_launch(void* const* d_in, const int* in_sizes, int n_in,
                              void* d_out, int out_size)
{
    const float* x    = (const float*)d_in[0];
    const float* box  = (const float*)d_in[1];
    const int*   bidx = (const int*)d_in[2];
    yolo_image_kernel<<<BATCH, 256>>>(x, box, bidx);
    yolo_reduce_kernel<<<1, 256>>>((float*)d_out);
}